// round 14
// baseline (speedup 1.0000x reference)
#include <cuda_runtime.h>
#include <cuda_fp16.h>
#include <mma.h>

using namespace nvcuda;

#define B_ 8
#define N_ 1024
#define C_ 256
#define HD_ 256   // H*D
#define NEG_SLOPE 0.2f
#define COMP_BLOCKS 256
#define PAD_IDX 192   // nnz = 1+Binom(1023,.05): mean 52, sigma 7; 192 is ~20 sigma

struct alignas(8) half4 { __half2 a, b; };

// Scratch (no cudaMalloc allowed)
__device__ __half g_Wxh[B_ * N_ * HD_];             // 16MB fp16
__device__ float  g_ei [B_ * N_ * 4];
__device__ float  g_ej [B_ * N_ * 4];
__device__ unsigned short g_idx[B_ * N_ * PAD_IDX]; // 3MB compacted neighbor lists
__device__ int    g_nnz[B_ * N_];

#define LDA 40   // 32 + 8 pad
#define LDB 72   // 64 + 8 pad
#define LDC 72

// ---------------------------------------------------------------------------
// Kernel 1: tf32 wmma GEMM + fused eij/fp16 epilogue (R8 exact internals —
// the 21.6us measured configuration).
// ---------------------------------------------------------------------------
__global__ void __launch_bounds__(256)
gemm_kernel(const float* __restrict__ A,
            const float* __restrict__ Bm,
            const float* __restrict__ attn_a,
            __half* __restrict__ Ch,
            float* __restrict__ ei,
            float* __restrict__ ej) {
    __shared__ __align__(16) char smem_buf[128 * LDC * 4];   // 36.9 KB
    float (*As)[LDA] = reinterpret_cast<float (*)[LDA]>(smem_buf);
    float (*Bs)[LDB] = reinterpret_cast<float (*)[LDB]>(smem_buf + 128 * LDA * 4);
    float (*Cs)[LDC] = reinterpret_cast<float (*)[LDC]>(smem_buf);

    const int tid = threadIdx.x;
    const int rowBase = blockIdx.x * 128;
    const int colBase = blockIdx.y * 64;
    const int h = blockIdx.y;

    const int w  = tid >> 5;
    const int wr = w >> 1;
    const int wc = w & 1;

    wmma::fragment<wmma::accumulator, 16, 16, 8, float> cf[2][2];
#pragma unroll
    for (int i = 0; i < 2; i++)
#pragma unroll
        for (int j = 0; j < 2; j++) wmma::fill_fragment(cf[i][j], 0.f);

    for (int kb = 0; kb < C_; kb += 32) {
#pragma unroll
        for (int u = 0; u < 4; u++) {
            int f = tid + u * 256;
            int row = f >> 3;
            int c0 = (f & 7) * 4;
            float4 v = *(const float4*)(A + (size_t)(rowBase + row) * C_ + kb + c0);
            As[row][c0 + 0] = wmma::__float_to_tf32(v.x);
            As[row][c0 + 1] = wmma::__float_to_tf32(v.y);
            As[row][c0 + 2] = wmma::__float_to_tf32(v.z);
            As[row][c0 + 3] = wmma::__float_to_tf32(v.w);
        }
#pragma unroll
        for (int u = 0; u < 2; u++) {
            int f = tid + u * 256;
            int r = f >> 4;
            int c0 = (f & 15) * 4;
            float4 v = *(const float4*)(Bm + (size_t)(kb + r) * HD_ + colBase + c0);
            Bs[r][c0 + 0] = wmma::__float_to_tf32(v.x);
            Bs[r][c0 + 1] = wmma::__float_to_tf32(v.y);
            Bs[r][c0 + 2] = wmma::__float_to_tf32(v.z);
            Bs[r][c0 + 3] = wmma::__float_to_tf32(v.w);
        }
        __syncthreads();

#pragma unroll
        for (int kk = 0; kk < 32; kk += 8) {
            wmma::fragment<wmma::matrix_a, 16, 16, 8, wmma::precision::tf32, wmma::row_major> af[2];
            wmma::fragment<wmma::matrix_b, 16, 16, 8, wmma::precision::tf32, wmma::row_major> bf[2];
#pragma unroll
            for (int i = 0; i < 2; i++)
                wmma::load_matrix_sync(af[i], &As[wr * 32 + i * 16][kk], LDA);
#pragma unroll
            for (int j = 0; j < 2; j++)
                wmma::load_matrix_sync(bf[j], &Bs[kk][wc * 32 + j * 16], LDB);
#pragma unroll
            for (int i = 0; i < 2; i++)
#pragma unroll
                for (int j = 0; j < 2; j++)
                    wmma::mma_sync(cf[i][j], af[i], bf[j], cf[i][j]);
        }
        __syncthreads();
    }

#pragma unroll
    for (int i = 0; i < 2; i++)
#pragma unroll
        for (int j = 0; j < 2; j++)
            wmma::store_matrix_sync(&Cs[wr * 32 + i * 16][wc * 32 + j * 16],
                                    cf[i][j], LDC, wmma::mem_row_major);
    __syncthreads();

    const int tx = tid & 15;
    const int ty = tid >> 4;
    const int lane = tid & 31;
    float4 ai4 = *(const float4*)(attn_a + h * 128 + tx * 4);
    float4 aj4 = *(const float4*)(attn_a + h * 128 + 64 + tx * 4);

#pragma unroll
    for (int i = 0; i < 8; i++) {
        const int r = ty * 8 + i;
        float4 c4 = *(const float4*)(&Cs[r][tx * 4]);

        size_t off = (size_t)(rowBase + r) * HD_ + colBase + tx * 4;
        half4 hv;
        hv.a = __floats2half2_rn(c4.x, c4.y);
        hv.b = __floats2half2_rn(c4.z, c4.w);
        *(half4*)(Ch + off) = hv;

        float pi = c4.x * ai4.x + c4.y * ai4.y + c4.z * ai4.z + c4.w * ai4.w;
        float pj = c4.x * aj4.x + c4.y * aj4.y + c4.z * aj4.z + c4.w * aj4.w;
#pragma unroll
        for (int o = 8; o > 0; o >>= 1) {
            pi += __shfl_xor_sync(0xffffffffu, pi, o);
            pj += __shfl_xor_sync(0xffffffffu, pj, o);
        }
        if ((lane & 15) == 0) {
            int row = rowBase + r;
            ei[row * 4 + h] = pi;
            ej[row * 4 + h] = pj;
        }
    }
}

// ---------------------------------------------------------------------------
// Kernel 1b (side stream): warp-per-row ballot compaction. No smem, no block
// barriers — pure streaming, overlaps the tensor-bound GEMM.
// ---------------------------------------------------------------------------
__global__ void __launch_bounds__(256)
compact_kernel(const float* __restrict__ adj) {
    const int lane = threadIdx.x & 31;
    const int gw   = (blockIdx.x << 3) + (threadIdx.x >> 5);  // global warp 0..2047
    const unsigned lt = (1u << lane) - 1u;

    for (int row = gw; row < B_ * N_; row += COMP_BLOCKS * 8) {
        const int n = row & 1023;
        const float4* adj_row4 = (const float4*)(adj + (size_t)row * N_);
        unsigned short* dst = g_idx + (size_t)row * PAD_IDX;

        int base = 0;
#pragma unroll
        for (int r = 0; r < 8; r++) {
            float4 v = adj_row4[r * 32 + lane];       // j = r*128 + lane*4 + c
            int j0 = r * 128 + lane * 4;
            unsigned m;
            bool p;
            p = (v.x != 0.f) || (j0 + 0 == n); m = __ballot_sync(0xffffffffu, p);
            { int q = base + __popc(m & lt); if (p && q < PAD_IDX) dst[q] = (unsigned short)(j0 + 0); }
            base += __popc(m);
            p = (v.y != 0.f) || (j0 + 1 == n); m = __ballot_sync(0xffffffffu, p);
            { int q = base + __popc(m & lt); if (p && q < PAD_IDX) dst[q] = (unsigned short)(j0 + 1); }
            base += __popc(m);
            p = (v.z != 0.f) || (j0 + 2 == n); m = __ballot_sync(0xffffffffu, p);
            { int q = base + __popc(m & lt); if (p && q < PAD_IDX) dst[q] = (unsigned short)(j0 + 2); }
            base += __popc(m);
            p = (v.w != 0.f) || (j0 + 3 == n); m = __ballot_sync(0xffffffffu, p);
            { int q = base + __popc(m & lt); if (p && q < PAD_IDX) dst[q] = (unsigned short)(j0 + 3); }
            base += __popc(m);
        }
        if (lane == 0) g_nnz[row] = min(base, PAD_IDX);
    }
}

// ---------------------------------------------------------------------------
// Kernel 2: GAT softmax + aggregation from precompacted lists (R10 exact —
// the 34.8us measured version, scalar idx load).
// ---------------------------------------------------------------------------
__global__ void __launch_bounds__(256)
gat_kernel(const __half* __restrict__ Wxh,
           const float* __restrict__ ei,
           const float* __restrict__ ej,
           float* __restrict__ out) {
    const int row = blockIdx.x;          // b*N + n
    const int b = row >> 10;
    const int t = threadIdx.x;
    const int lane = t & 31, w = t >> 5;

    __shared__ unsigned short s_idx[PAD_IDX];
    __shared__ float  s_e[PAD_IDX * 4];
    __shared__ float  s_red[256 * 4];
    __shared__ float4 s_wred[8];
    __shared__ float4 s_bcast;
    __shared__ int    s_nnz;

    if (t == 0) s_nnz = g_nnz[row];
    if (t < PAD_IDX) s_idx[t] = g_idx[(size_t)row * PAD_IDX + t];
    __syncthreads();
    const int nnz = s_nnz;

    // --- exp(leaky(ei+ej)) + per-head sum (single shot: nnz <= 192 < 256) ---
    float4 ei4 = *(const float4*)(ei + (size_t)row * 4);
    float4 t4 = make_float4(0.f, 0.f, 0.f, 0.f);
    if (t < nnz) {
        int j = s_idx[t];
        float4 e4 = *(const float4*)(ej + (size_t)((b << 10) + j) * 4);
        e4.x += ei4.x; e4.y += ei4.y; e4.z += ei4.z; e4.w += ei4.w;
        e4.x = e4.x > 0.f ? e4.x : NEG_SLOPE * e4.x;
        e4.y = e4.y > 0.f ? e4.y : NEG_SLOPE * e4.y;
        e4.z = e4.z > 0.f ? e4.z : NEG_SLOPE * e4.z;
        e4.w = e4.w > 0.f ? e4.w : NEG_SLOPE * e4.w;
        e4.x = __expf(e4.x); e4.y = __expf(e4.y);
        e4.z = __expf(e4.z); e4.w = __expf(e4.w);
        t4 = e4;
        ((float4*)s_e)[t] = e4;
    }
#pragma unroll
    for (int o = 16; o > 0; o >>= 1) {
        t4.x += __shfl_xor_sync(0xffffffffu, t4.x, o);
        t4.y += __shfl_xor_sync(0xffffffffu, t4.y, o);
        t4.z += __shfl_xor_sync(0xffffffffu, t4.z, o);
        t4.w += __shfl_xor_sync(0xffffffffu, t4.w, o);
    }
    if (lane == 0) s_wred[w] = t4;
    __syncthreads();
    if (t == 0) {
        float4 r = s_wred[0];
#pragma unroll
        for (int i = 1; i < 8; i++) {
            float4 v = s_wred[i];
            r.x += v.x; r.y += v.y; r.z += v.z; r.w += v.w;
        }
        s_bcast = r;
    }
    __syncthreads();
    float4 sm = s_bcast;

    // --- aggregation: 4 neighbor-groups x 64 threads, 4 fp16 cols/thread ---
    const int g = t >> 6;
    const int q = t & 63;
    const int h = q >> 4;
    float4 acc = make_float4(0.f, 0.f, 0.f, 0.f);
    const __half* WxB = Wxh + (size_t)b * N_ * HD_ + q * 4;
#pragma unroll 4
    for (int k = g; k < nnz; k += 4) {
        int j = s_idx[k];
        float c = s_e[k * 4 + h];
        half4 rv = *(const half4*)(WxB + (size_t)j * HD_);
        float2 f0 = __half22float2(rv.a);
        float2 f1 = __half22float2(rv.b);
        acc.x += c * f0.x; acc.y += c * f0.y;
        acc.z += c * f1.x; acc.w += c * f1.y;
    }
    ((float4*)s_red)[t] = acc;
    __syncthreads();
    if (t < 64) {
        float4 a0 = ((float4*)s_red)[t];
        float4 a1 = ((float4*)s_red)[64 + t];
        float4 a2 = ((float4*)s_red)[128 + t];
        float4 a3 = ((float4*)s_red)[192 + t];
        const int hh = t >> 4;
        float sum_h = (hh == 0) ? sm.x : (hh == 1) ? sm.y : (hh == 2) ? sm.z : sm.w;
        float rs = 1.f / sum_h;
        float4 o;
        o.x = (a0.x + a1.x + a2.x + a3.x) * rs;
        o.y = (a0.y + a1.y + a2.y + a3.y) * rs;
        o.z = (a0.z + a1.z + a2.z + a3.z) * rs;
        o.w = (a0.w + a1.w + a2.w + a3.w) * rs;
        ((float4*)(out + (size_t)row * HD_))[t] = o;
    }
}

// ---------------------------------------------------------------------------
// Launch: gemm first (sparse 256-CTA wave), then compaction forked onto a
// side stream so its DRAM streaming backfills idle SM slots under the GEMM.
// ---------------------------------------------------------------------------
extern "C" void kernel_launch(void* const* d_in, const int* in_sizes, int n_in,
                              void* d_out, int out_size) {
    const float* x   = (const float*)d_in[0];   // (8,1024,256)
    const float* adj = (const float*)d_in[1];   // (8,1024,1024)
    const float* W   = (const float*)d_in[2];   // (256,256)
    const float* a   = (const float*)d_in[3];   // (1,4,128)
    float* out = (float*)d_out;

    __half* Wxh; cudaGetSymbolAddress((void**)&Wxh, g_Wxh);
    float*  ei;  cudaGetSymbolAddress((void**)&ei,  g_ei);
    float*  ej;  cudaGetSymbolAddress((void**)&ej,  g_ej);

    cudaStream_t side;
    cudaStreamCreateWithFlags(&side, cudaStreamNonBlocking);
    cudaEvent_t evFork, evJoin;
    cudaEventCreateWithFlags(&evFork, cudaEventDisableTiming);
    cudaEventCreateWithFlags(&evJoin, cudaEventDisableTiming);

    // fork BEFORE gemm so both kernels are adjacent graph nodes...
    cudaEventRecord(evFork, 0);
    cudaStreamWaitEvent(side, evFork, 0);

    // ...but enqueue gemm on the main stream FIRST so it owns the machine,
    // with compaction backfilling.
    dim3 ggrid(B_ * N_ / 128, HD_ / 64);
    gemm_kernel<<<ggrid, 256>>>(x, W, a, Wxh, ei, ej);

    compact_kernel<<<COMP_BLOCKS, 256, 0, side>>>(adj);

    // join: main stream waits for compaction before gat
    cudaEventRecord(evJoin, side);
    cudaStreamWaitEvent(0, evJoin, 0);

    gat_kernel<<<B_ * N_, 256>>>(Wxh, ei, ej, out);

    cudaEventDestroy(evFork);
    cudaEventDestroy(evJoin);
    cudaStreamDestroy(side);
}

// round 15
// speedup vs baseline: 1.6192x; 1.6192x over previous
#include <cuda_runtime.h>
#include <cuda_fp16.h>
#include <mma.h>

using namespace nvcuda;

#define B_ 8
#define N_ 1024
#define C_ 256
#define HD_ 256   // H*D
#define NEG_SLOPE 0.2f

struct alignas(8) half4 { __half2 a, b; };

// Scratch (no cudaMalloc allowed)
__device__ __half g_Wxh[B_ * N_ * HD_];     // 16MB fp16
__device__ float  g_ei [B_ * N_ * 4];
__device__ float  g_ej [B_ * N_ * 4];

#define BK  16
#define LDA 24   // 16 + 8 pad
#define LDB 72   // 64 + 8 pad
#define LDC 72

__device__ __forceinline__ void cp_async16(void* smem_dst, const void* gsrc) {
    unsigned saddr = (unsigned)__cvta_generic_to_shared(smem_dst);
    asm volatile("cp.async.cg.shared.global [%0], [%1], 16;\n" :: "r"(saddr), "l"(gsrc));
}

// ---------------------------------------------------------------------------
// Kernel 1: tf32 wmma GEMM + fused eij/fp16 epilogue.
// cp.async double-buffered mainloop (BK=16, 2 stages) — global-load latency
// hidden behind tensor work. Fragment-level RN tf32 conversion keeps
// precision identical to R8.
// ---------------------------------------------------------------------------
__global__ void __launch_bounds__(256)
gemm_kernel(const float* __restrict__ A,
            const float* __restrict__ Bm,
            const float* __restrict__ attn_a,
            __half* __restrict__ Ch,
            float* __restrict__ ei,
            float* __restrict__ ej) {
    // union buffer: {As(2 stages), Bs(2 stages)} mainloop / Cs epilogue
    __shared__ __align__(16) char smem_buf[128 * LDC * 4];   // 36.9 KB
    float (*As)[128][LDA] = reinterpret_cast<float (*)[128][LDA]>(smem_buf);               // [2][128][LDA]
    float (*Bs)[BK][LDB]  = reinterpret_cast<float (*)[BK][LDB]>(smem_buf + 2 * 128 * LDA * 4);
    float (*Cs)[LDC]      = reinterpret_cast<float (*)[LDC]>(smem_buf);                    // [128][LDC]

    const int tid = threadIdx.x;
    const int rowBase = blockIdx.x * 128;
    const int colBase = blockIdx.y * 64;
    const int h = blockIdx.y;

    const int w  = tid >> 5;
    const int wr = w >> 1;       // warp row 0..3 (32 rows)
    const int wc = w & 1;        // warp col 0..1 (32 cols)

    // per-thread cp.async coordinates
    const int aRow0 = tid >> 2;              // +0, +64
    const int aCol  = (tid & 3) * 4;
    const int bRow  = tid >> 4;
    const int bCol  = (tid & 15) * 4;

    wmma::fragment<wmma::accumulator, 16, 16, 8, float> cf[2][2];
#pragma unroll
    for (int i = 0; i < 2; i++)
#pragma unroll
        for (int j = 0; j < 2; j++) wmma::fill_fragment(cf[i][j], 0.f);

    // prologue: stage 0
    {
        cp_async16(&As[0][aRow0][aCol],      A + (size_t)(rowBase + aRow0) * C_ + aCol);
        cp_async16(&As[0][aRow0 + 64][aCol], A + (size_t)(rowBase + aRow0 + 64) * C_ + aCol);
        cp_async16(&Bs[0][bRow][bCol],       Bm + (size_t)bRow * HD_ + colBase + bCol);
        asm volatile("cp.async.commit_group;\n");
    }

    const int NIT = C_ / BK;     // 16
    for (int it = 0; it < NIT; it++) {
        const int cur = it & 1;
        if (it + 1 < NIT) {
            const int nxt = (it + 1) & 1;
            const int kb = (it + 1) * BK;
            cp_async16(&As[nxt][aRow0][aCol],      A + (size_t)(rowBase + aRow0) * C_ + kb + aCol);
            cp_async16(&As[nxt][aRow0 + 64][aCol], A + (size_t)(rowBase + aRow0 + 64) * C_ + kb + aCol);
            cp_async16(&Bs[nxt][bRow][bCol],       Bm + (size_t)(kb + bRow) * HD_ + colBase + bCol);
            asm volatile("cp.async.commit_group;\n");
            asm volatile("cp.async.wait_group 1;\n");
        } else {
            asm volatile("cp.async.wait_group 0;\n");
        }
        __syncthreads();

#pragma unroll
        for (int kk = 0; kk < BK; kk += 8) {
            wmma::fragment<wmma::matrix_a, 16, 16, 8, wmma::precision::tf32, wmma::row_major> af[2];
            wmma::fragment<wmma::matrix_b, 16, 16, 8, wmma::precision::tf32, wmma::row_major> bf[2];
#pragma unroll
            for (int i = 0; i < 2; i++) {
                wmma::load_matrix_sync(af[i], &As[cur][wr * 32 + i * 16][kk], LDA);
#pragma unroll
                for (int e = 0; e < af[i].num_elements; e++)
                    af[i].x[e] = wmma::__float_to_tf32(af[i].x[e]);
            }
#pragma unroll
            for (int j = 0; j < 2; j++) {
                wmma::load_matrix_sync(bf[j], &Bs[cur][kk][wc * 32 + j * 16], LDB);
#pragma unroll
                for (int e = 0; e < bf[j].num_elements; e++)
                    bf[j].x[e] = wmma::__float_to_tf32(bf[j].x[e]);
            }
#pragma unroll
            for (int i = 0; i < 2; i++)
#pragma unroll
                for (int j = 0; j < 2; j++)
                    wmma::mma_sync(cf[i][j], af[i], bf[j], cf[i][j]);
        }
        __syncthreads();
    }

    // stage C to smem (overwrites stage buffers)
#pragma unroll
    for (int i = 0; i < 2; i++)
#pragma unroll
        for (int j = 0; j < 2; j++)
            wmma::store_matrix_sync(&Cs[wr * 32 + i * 16][wc * 32 + j * 16],
                                    cf[i][j], LDC, wmma::mem_row_major);
    __syncthreads();

    // epilogue: fp16 store + eij (R8 mapping)
    const int tx = tid & 15;
    const int ty = tid >> 4;
    const int lane = tid & 31;
    float4 ai4 = *(const float4*)(attn_a + h * 128 + tx * 4);
    float4 aj4 = *(const float4*)(attn_a + h * 128 + 64 + tx * 4);

#pragma unroll
    for (int i = 0; i < 8; i++) {
        const int r = ty * 8 + i;
        float4 c4 = *(const float4*)(&Cs[r][tx * 4]);

        size_t off = (size_t)(rowBase + r) * HD_ + colBase + tx * 4;
        half4 hv;
        hv.a = __floats2half2_rn(c4.x, c4.y);
        hv.b = __floats2half2_rn(c4.z, c4.w);
        *(half4*)(Ch + off) = hv;

        float pi = c4.x * ai4.x + c4.y * ai4.y + c4.z * ai4.z + c4.w * ai4.w;
        float pj = c4.x * aj4.x + c4.y * aj4.y + c4.z * aj4.z + c4.w * aj4.w;
#pragma unroll
        for (int o = 8; o > 0; o >>= 1) {
            pi += __shfl_xor_sync(0xffffffffu, pi, o);
            pj += __shfl_xor_sync(0xffffffffu, pj, o);
        }
        if ((lane & 15) == 0) {
            int row = rowBase + r;
            ei[row * 4 + h] = pi;
            ej[row * 4 + h] = pj;
        }
    }
}

// ---------------------------------------------------------------------------
// Kernel 2: block-per-row GAT with inline compaction (R8 exact — the 39.5us
// measured version; compaction amortizes inside the kernel's own latency).
// ---------------------------------------------------------------------------
__global__ void __launch_bounds__(256)
gat_kernel(const float* __restrict__ adj,
           const __half* __restrict__ Wxh,
           const float* __restrict__ ei,
           const float* __restrict__ ej,
           float* __restrict__ out) {
    const int b = blockIdx.x >> 10;
    const int n = blockIdx.x & 1023;
    const int t = threadIdx.x;
    const int lane = t & 31, w = t >> 5;

    __shared__ unsigned short s_idx[N_];
    __shared__ float s_e[N_ * 4];
    __shared__ float s_red[256 * 4];
    __shared__ int   s_warp[8];
    __shared__ int   s_off[9];
    __shared__ float4 s_wred[8];
    __shared__ float4 s_bcast;

    const float* adj_row = adj + ((size_t)(b * N_ + n)) * N_;

    // --- deterministic compaction of nonzero neighbors (incl. self) ---
    const int jb = t * 4;
    float4 av4 = *(const float4*)(adj_row + jb);
    bool p[4];
    p[0] = (av4.x != 0.f) || (jb + 0 == n);
    p[1] = (av4.y != 0.f) || (jb + 1 == n);
    p[2] = (av4.z != 0.f) || (jb + 2 == n);
    p[3] = (av4.w != 0.f) || (jb + 3 == n);
    int cnt = (p[0] ? 1 : 0) + (p[1] ? 1 : 0) + (p[2] ? 1 : 0) + (p[3] ? 1 : 0);

    int x = cnt;
#pragma unroll
    for (int o = 1; o < 32; o <<= 1) {
        int y = __shfl_up_sync(0xffffffffu, x, o);
        if (lane >= o) x += y;
    }
    if (lane == 31) s_warp[w] = x;
    __syncthreads();
    if (t == 0) {
        int s = 0;
#pragma unroll
        for (int i = 0; i < 8; i++) { s_off[i] = s; s += s_warp[i]; }
        s_off[8] = s;
    }
    __syncthreads();
    int pos = s_off[w] + x - cnt;
#pragma unroll
    for (int i = 0; i < 4; i++) {
        if (p[i]) s_idx[pos++] = (unsigned short)(jb + i);
    }
    const int nnz = s_off[8];
    __syncthreads();

    // --- single pass: exp(leaky(ei+ej)) + per-head sum ---
    float4 ei4 = *(const float4*)(ei + (size_t)(b * N_ + n) * 4);
    float4 t4 = make_float4(0.f, 0.f, 0.f, 0.f);
    for (int k = t; k < nnz; k += 256) {
        int j = s_idx[k];
        float4 e4 = *(const float4*)(ej + (size_t)(b * N_ + j) * 4);
        e4.x += ei4.x; e4.y += ei4.y; e4.z += ei4.z; e4.w += ei4.w;
        e4.x = e4.x > 0.f ? e4.x : NEG_SLOPE * e4.x;
        e4.y = e4.y > 0.f ? e4.y : NEG_SLOPE * e4.y;
        e4.z = e4.z > 0.f ? e4.z : NEG_SLOPE * e4.z;
        e4.w = e4.w > 0.f ? e4.w : NEG_SLOPE * e4.w;
        e4.x = __expf(e4.x); e4.y = __expf(e4.y);
        e4.z = __expf(e4.z); e4.w = __expf(e4.w);
        t4.x += e4.x; t4.y += e4.y; t4.z += e4.z; t4.w += e4.w;
        ((float4*)s_e)[k] = e4;
    }
#pragma unroll
    for (int o = 16; o > 0; o >>= 1) {
        t4.x += __shfl_xor_sync(0xffffffffu, t4.x, o);
        t4.y += __shfl_xor_sync(0xffffffffu, t4.y, o);
        t4.z += __shfl_xor_sync(0xffffffffu, t4.z, o);
        t4.w += __shfl_xor_sync(0xffffffffu, t4.w, o);
    }
    if (lane == 0) s_wred[w] = t4;
    __syncthreads();
    if (t == 0) {
        float4 r = s_wred[0];
#pragma unroll
        for (int i = 1; i < 8; i++) {
            float4 v = s_wred[i];
            r.x += v.x; r.y += v.y; r.z += v.z; r.w += v.w;
        }
        s_bcast = r;
    }
    __syncthreads();
    float4 sm = s_bcast;

    // --- aggregation: 4 neighbor-groups x 64 threads, 4 fp16 cols/thread ---
    const int g = t >> 6;
    const int q = t & 63;
    const int h = q >> 4;
    float4 acc = make_float4(0.f, 0.f, 0.f, 0.f);
    const __half* WxB = Wxh + (size_t)b * N_ * HD_ + q * 4;
#pragma unroll 4
    for (int k = g; k < nnz; k += 4) {
        int j = s_idx[k];
        float c = s_e[k * 4 + h];
        half4 rv = *(const half4*)(WxB + (size_t)j * HD_);
        float2 f0 = __half22float2(rv.a);
        float2 f1 = __half22float2(rv.b);
        acc.x += c * f0.x; acc.y += c * f0.y;
        acc.z += c * f1.x; acc.w += c * f1.y;
    }
    ((float4*)s_red)[t] = acc;
    __syncthreads();
    if (t < 64) {
        float4 a0 = ((float4*)s_red)[t];
        float4 a1 = ((float4*)s_red)[64 + t];
        float4 a2 = ((float4*)s_red)[128 + t];
        float4 a3 = ((float4*)s_red)[192 + t];
        const int hh = t >> 4;
        float sum_h = (hh == 0) ? sm.x : (hh == 1) ? sm.y : (hh == 2) ? sm.z : sm.w;
        float rs = 1.f / sum_h;
        float4 o;
        o.x = (a0.x + a1.x + a2.x + a3.x) * rs;
        o.y = (a0.y + a1.y + a2.y + a3.y) * rs;
        o.z = (a0.z + a1.z + a2.z + a3.z) * rs;
        o.w = (a0.w + a1.w + a2.w + a3.w) * rs;
        ((float4*)(out + (size_t)(b * N_ + n) * HD_))[t] = o;
    }
}

// ---------------------------------------------------------------------------
extern "C" void kernel_launch(void* const* d_in, const int* in_sizes, int n_in,
                              void* d_out, int out_size) {
    const float* x   = (const float*)d_in[0];   // (8,1024,256)
    const float* adj = (const float*)d_in[1];   // (8,1024,1024)
    const float* W   = (const float*)d_in[2];   // (256,256)
    const float* a   = (const float*)d_in[3];   // (1,4,128)
    float* out = (float*)d_out;

    __half* Wxh; cudaGetSymbolAddress((void**)&Wxh, g_Wxh);
    float*  ei;  cudaGetSymbolAddress((void**)&ei,  g_ei);
    float*  ej;  cudaGetSymbolAddress((void**)&ej,  g_ej);

    dim3 ggrid(B_ * N_ / 128, HD_ / 64);
    gemm_kernel<<<ggrid, 256>>>(x, W, a, Wxh, ei, ej);
    gat_kernel<<<B_ * N_, 256>>>(adj, Wxh, ei, ej, out);
}